// round 2
// baseline (speedup 1.0000x reference)
#include <cuda_runtime.h>
#include <math.h>

#define HDIM 128
#define LLAYERS 5
#define NMAX 100000
#define EMAX 200000
#define GMAX 2000

// ---------------- scratch (static device globals; no allocation) ----------------
__device__ float    g_h[NMAX * HDIM];
__device__ float    g_z[NMAX * HDIM];
__device__ float    g_etab[LLAYERS * 24 * HDIM];
__device__ float    g_msum[GMAX * HDIM];
__device__ unsigned g_mmax[GMAX * HDIM];
__device__ int      g_cnt[GMAX];
__device__ float    g_gemb[GMAX * 256];
__device__ float    g_ex1[GMAX * HDIM];
__device__ float    g_ex2[GMAX * HDIM];
__device__ float    g_comb[GMAX * 384];
__device__ float    g_o1[GMAX * 256];
__device__ float    g_o2[GMAX * 128];

// ---------------- helpers ----------------
__device__ __forceinline__ unsigned encf(float f) {
    unsigned u = __float_as_uint(f);
    return (u & 0x80000000u) ? ~u : (u | 0x80000000u);
}
__device__ __forceinline__ float decf(unsigned u) {
    return (u & 0x80000000u) ? __uint_as_float(u & 0x7FFFFFFFu) : __uint_as_float(~u);
}

// ---------------- fused 2-GEMM MLP: Y = epilogue( relu(A@W1+b1) @ W2 + b2 ) ------
// A: [N, K1] row-major. W1: [K1,128], W2: [128,128].
// LAYER=true : H_out[r] = relu( (t@W2+b2) * (gamma*bnscale) + beta ) + H_out[r]  (in-place residual)
// LAYER=false: H_out[r] = t@W2+b2
template <int K1, bool LAYER>
__global__ __launch_bounds__(256, 1)
void mlp2_kernel(const float* __restrict__ A, int N,
                 const float* __restrict__ W1, const float* __restrict__ b1,
                 const float* __restrict__ W2, const float* __restrict__ b2,
                 const float* __restrict__ gamma, const float* __restrict__ beta,
                 float bnscale, float* __restrict__ H)
{
    extern __shared__ float sm[];
    float* As = sm;              // 128*128 floats (64KB)
    float* Ws = sm + 128 * 128;  // 128*128 floats (64KB)
    const int tid = threadIdx.x;
    const int tx = tid & 15;     // col group: cols tx*8 .. tx*8+7
    const int ty = tid >> 4;     // row group: rows ty*8 .. ty*8+7
    const int n0 = blockIdx.x * 128;

    // load A tile [128 x K1] into As[r*128 + k]
    {
        const int KQ = K1 / 4;
        #pragma unroll
        for (int i = 0; i < (128 * KQ) / 256; i++) {
            int idx = tid + i * 256;
            int r = idx / KQ, kq = idx % KQ;
            float4 v = make_float4(0.f, 0.f, 0.f, 0.f);
            if (n0 + r < N) v = *(const float4*)(A + (size_t)(n0 + r) * K1 + kq * 4);
            *(float4*)(As + r * 128 + kq * 4) = v;
        }
    }
    // load W1 [K1 x 128] into Ws (row-major, contiguous)
    {
        #pragma unroll
        for (int i = 0; i < K1 / 8; i++) {
            int idx = tid + i * 256;
            *(float4*)(Ws + idx * 4) = *(const float4*)(W1 + idx * 4);
        }
    }
    __syncthreads();

    float acc[8][8];
    #pragma unroll
    for (int i = 0; i < 8; i++)
        #pragma unroll
        for (int j = 0; j < 8; j++) acc[i][j] = 0.f;

    // GEMM1: acc = A_tile @ W1
    #pragma unroll 2
    for (int kk = 0; kk < K1; kk += 4) {
        float a[8][4], b[4][8];
        #pragma unroll
        for (int i = 0; i < 8; i++) {
            float4 v = *(const float4*)(As + (ty * 8 + i) * 128 + kk);
            a[i][0] = v.x; a[i][1] = v.y; a[i][2] = v.z; a[i][3] = v.w;
        }
        #pragma unroll
        for (int q = 0; q < 4; q++) {
            float4 v0 = *(const float4*)(Ws + (kk + q) * 128 + tx * 8);
            float4 v1 = *(const float4*)(Ws + (kk + q) * 128 + tx * 8 + 4);
            b[q][0] = v0.x; b[q][1] = v0.y; b[q][2] = v0.z; b[q][3] = v0.w;
            b[q][4] = v1.x; b[q][5] = v1.y; b[q][6] = v1.z; b[q][7] = v1.w;
        }
        #pragma unroll
        for (int i = 0; i < 8; i++)
            #pragma unroll
            for (int j = 0; j < 8; j++)
                acc[i][j] += a[i][0] * b[0][j] + a[i][1] * b[1][j]
                           + a[i][2] * b[2][j] + a[i][3] * b[3][j];
    }
    __syncthreads();

    // T = relu(acc + b1) -> As ; load W2 -> Ws
    {
        float bb[8];
        #pragma unroll
        for (int j = 0; j < 8; j++) bb[j] = __ldg(b1 + tx * 8 + j);
        #pragma unroll
        for (int i = 0; i < 8; i++) {
            float4 v0, v1;
            v0.x = fmaxf(acc[i][0] + bb[0], 0.f);
            v0.y = fmaxf(acc[i][1] + bb[1], 0.f);
            v0.z = fmaxf(acc[i][2] + bb[2], 0.f);
            v0.w = fmaxf(acc[i][3] + bb[3], 0.f);
            v1.x = fmaxf(acc[i][4] + bb[4], 0.f);
            v1.y = fmaxf(acc[i][5] + bb[5], 0.f);
            v1.z = fmaxf(acc[i][6] + bb[6], 0.f);
            v1.w = fmaxf(acc[i][7] + bb[7], 0.f);
            *(float4*)(As + (ty * 8 + i) * 128 + tx * 8) = v0;
            *(float4*)(As + (ty * 8 + i) * 128 + tx * 8 + 4) = v1;
        }
        #pragma unroll
        for (int i = 0; i < 16; i++) {
            int idx = tid + i * 256;
            *(float4*)(Ws + idx * 4) = *(const float4*)(W2 + idx * 4);
        }
    }
    __syncthreads();

    // GEMM2: acc = T @ W2  (K = 128)
    #pragma unroll
    for (int i = 0; i < 8; i++)
        #pragma unroll
        for (int j = 0; j < 8; j++) acc[i][j] = 0.f;

    #pragma unroll 2
    for (int kk = 0; kk < 128; kk += 4) {
        float a[8][4], b[4][8];
        #pragma unroll
        for (int i = 0; i < 8; i++) {
            float4 v = *(const float4*)(As + (ty * 8 + i) * 128 + kk);
            a[i][0] = v.x; a[i][1] = v.y; a[i][2] = v.z; a[i][3] = v.w;
        }
        #pragma unroll
        for (int q = 0; q < 4; q++) {
            float4 v0 = *(const float4*)(Ws + (kk + q) * 128 + tx * 8);
            float4 v1 = *(const float4*)(Ws + (kk + q) * 128 + tx * 8 + 4);
            b[q][0] = v0.x; b[q][1] = v0.y; b[q][2] = v0.z; b[q][3] = v0.w;
            b[q][4] = v1.x; b[q][5] = v1.y; b[q][6] = v1.z; b[q][7] = v1.w;
        }
        #pragma unroll
        for (int i = 0; i < 8; i++)
            #pragma unroll
            for (int j = 0; j < 8; j++)
                acc[i][j] += a[i][0] * b[0][j] + a[i][1] * b[1][j]
                           + a[i][2] * b[2][j] + a[i][3] * b[3][j];
    }

    // epilogue
    float b2v[8];
    #pragma unroll
    for (int j = 0; j < 8; j++) b2v[j] = __ldg(b2 + tx * 8 + j);
    if (LAYER) {
        float gm[8], bt[8];
        #pragma unroll
        for (int j = 0; j < 8; j++) {
            gm[j] = __ldg(gamma + tx * 8 + j) * bnscale;
            bt[j] = __ldg(beta + tx * 8 + j);
        }
        #pragma unroll
        for (int i = 0; i < 8; i++) {
            int r = n0 + ty * 8 + i;
            if (r < N) {
                float* hp = H + (size_t)r * 128 + tx * 8;
                float4 h0 = *(float4*)hp;
                float4 h1 = *(float4*)(hp + 4);
                float o[8];
                #pragma unroll
                for (int j = 0; j < 8; j++) {
                    float zz = acc[i][j] + b2v[j];
                    zz = zz * gm[j] + bt[j];
                    o[j] = fmaxf(zz, 0.f);
                }
                h0.x += o[0]; h0.y += o[1]; h0.z += o[2]; h0.w += o[3];
                h1.x += o[4]; h1.y += o[5]; h1.z += o[6]; h1.w += o[7];
                *(float4*)hp = h0;
                *(float4*)(hp + 4) = h1;
            }
        }
    } else {
        #pragma unroll
        for (int i = 0; i < 8; i++) {
            int r = n0 + ty * 8 + i;
            if (r < N) {
                float* hp = H + (size_t)r * 128 + tx * 8;
                float4 h0, h1;
                h0.x = acc[i][0] + b2v[0]; h0.y = acc[i][1] + b2v[1];
                h0.z = acc[i][2] + b2v[2]; h0.w = acc[i][3] + b2v[3];
                h1.x = acc[i][4] + b2v[4]; h1.y = acc[i][5] + b2v[5];
                h1.z = acc[i][6] + b2v[6]; h1.w = acc[i][7] + b2v[7];
                *(float4*)hp = h0;
                *(float4*)(hp + 4) = h1;
            }
        }
    }
}

// ---------------- edge-type table: etab[l][t] = (te[bt]+de[bd]) @ lew[l] + leb[l] --
__global__ void etab_kernel(const float* __restrict__ te, const float* __restrict__ de,
                            const float* __restrict__ lew, const float* __restrict__ leb)
{
    int l = blockIdx.x / 24, t = blockIdx.x % 24;
    int bt = t / 4, bd = t % 4;
    int c = threadIdx.x;
    float s = leb[l * 128 + c];
    #pragma unroll 4
    for (int k = 0; k < 64; k++) {
        float ev = te[bt * 64 + k] + de[bd * 64 + k];
        s += ev * __ldg(lew + (size_t)(l * 64 + k) * 128 + c);
    }
    g_etab[(l * 24 + t) * 128 + c] = s;
}

// ---------------- z <- h (float4 copy) ----------------
__global__ void copy_kernel(const float* __restrict__ src, float* __restrict__ dst, int n4)
{
    int idx = blockIdx.x * blockDim.x + threadIdx.x;
    if (idx < n4) ((float4*)dst)[idx] = ((const float4*)src)[idx];
}

// ---------------- message + scatter: z[dst] += relu(h[src] + etab[type]) ----------
__global__ void msg_kernel(const int* __restrict__ ei, const int* __restrict__ ea,
                           const float* __restrict__ etab_l, int E,
                           const float* __restrict__ h, float* __restrict__ z)
{
    int e = blockIdx.x * 8 + (threadIdx.x >> 5);
    if (e >= E) return;
    int lane = threadIdx.x & 31;
    int src = ei[e], dst = ei[E + e];
    int bt = ea[2 * e], bd = ea[2 * e + 1];
    bt = min(max(bt, 0), 5);
    bd = min(max(bd, 0), 3);
    const float* et = etab_l + (bt * 4 + bd) * 128;
    float4 hv = *(const float4*)(h + (size_t)src * 128 + lane * 4);
    float4 ev = *(const float4*)(et + lane * 4);
    float m0 = fmaxf(hv.x + ev.x, 0.f);
    float m1 = fmaxf(hv.y + ev.y, 0.f);
    float m2 = fmaxf(hv.z + ev.z, 0.f);
    float m3 = fmaxf(hv.w + ev.w, 0.f);
    float* zp = z + (size_t)dst * 128 + lane * 4;
    atomicAdd(zp + 0, m0);
    atomicAdd(zp + 1, m1);
    atomicAdd(zp + 2, m2);
    atomicAdd(zp + 3, m3);
}

// ---------------- pooling ----------------
__global__ void pool_init_kernel(int G)
{
    int idx = blockIdx.x * blockDim.x + threadIdx.x;
    if (idx < G * 128) { g_msum[idx] = 0.f; g_mmax[idx] = 0u; }
    if (idx < G) g_cnt[idx] = 0;
}

__global__ void pool_kernel(const float* __restrict__ h, const int* __restrict__ batch, int N)
{
    int idx = blockIdx.x * blockDim.x + threadIdx.x;
    if (idx >= N * 32) return;
    int n = idx >> 5, c4 = idx & 31;
    int g = __ldg(batch + n);
    float4 v = *(const float4*)(h + (size_t)n * 128 + c4 * 4);
    float* ms = &g_msum[g * 128 + c4 * 4];
    atomicAdd(ms + 0, v.x); atomicAdd(ms + 1, v.y);
    atomicAdd(ms + 2, v.z); atomicAdd(ms + 3, v.w);
    unsigned* mm = &g_mmax[g * 128 + c4 * 4];
    atomicMax(mm + 0, encf(v.x)); atomicMax(mm + 1, encf(v.y));
    atomicMax(mm + 2, encf(v.z)); atomicMax(mm + 3, encf(v.w));
    if (c4 == 0) atomicAdd(&g_cnt[g], 1);
}

__global__ void pool_fin_kernel(int G, float* __restrict__ out_ge)
{
    int idx = blockIdx.x * blockDim.x + threadIdx.x;
    if (idx >= G * 128) return;
    int g = idx / 128, c = idx % 128;
    float mean = g_msum[idx] / (float)g_cnt[g];
    float mx = decf(g_mmax[idx]);
    g_gemb[g * 256 + c] = mean;
    g_gemb[g * 256 + 128 + c] = mx;
    out_ge[g * 256 + c] = mean;
    out_ge[g * 256 + 128 + c] = mx;
}

// ---------------- small dense layers (naive, tiny G) ----------------
__global__ void dense_relu_kernel(const float* __restrict__ X, const float* __restrict__ W,
                                  const float* __restrict__ b, float* __restrict__ Y,
                                  int G, int K, int C)
{
    int idx = blockIdx.x * blockDim.x + threadIdx.x;
    if (idx >= G * C) return;
    int g = idx / C, c = idx % C;
    float s = __ldg(b + c);
    #pragma unroll 4
    for (int k = 0; k < K; k++)
        s += __ldg(X + (size_t)g * K + k) * __ldg(W + (size_t)k * C + c);
    Y[idx] = fmaxf(s, 0.f);
}

__global__ void comb_kernel(int G, float* __restrict__ out_comb)
{
    int idx = blockIdx.x * blockDim.x + threadIdx.x;
    if (idx >= G * 384) return;
    int g = idx / 384, c = idx % 384;
    float v = (c < 256) ? g_gemb[g * 256 + c] : g_ex2[g * 128 + (c - 256)];
    g_comb[idx] = v;
    out_comb[idx] = v;
}

__global__ void head3_kernel(int G, const float* __restrict__ hw3,
                             const float* __restrict__ hb3, float* __restrict__ out)
{
    int g = blockIdx.x * blockDim.x + threadIdx.x;
    if (g >= G) return;
    float s = __ldg(hb3);
    #pragma unroll 4
    for (int k = 0; k < 128; k++)
        s += g_o2[g * 128 + k] * __ldg(hw3 + k);
    out[g] = s;
}

// ---------------- launch ----------------
extern "C" void kernel_launch(void* const* d_in, const int* in_sizes, int n_in,
                              void* d_out, int out_size)
{
    const float* x     = (const float*)d_in[0];
    const int*   ei    = (const int*)d_in[1];
    const int*   ea    = (const int*)d_in[2];
    const int*   batch = (const int*)d_in[3];
    const float* expf_ = (const float*)d_in[4];
    const float* nw1 = (const float*)d_in[5];
    const float* nb1 = (const float*)d_in[6];
    const float* nw2 = (const float*)d_in[7];
    const float* nb2 = (const float*)d_in[8];
    const float* te  = (const float*)d_in[9];
    const float* de  = (const float*)d_in[10];
    const float* lew = (const float*)d_in[11];
    const float* leb = (const float*)d_in[12];
    const float* mw1 = (const float*)d_in[13];
    const float* mb1 = (const float*)d_in[14];
    const float* mw2 = (const float*)d_in[15];
    const float* mb2 = (const float*)d_in[16];
    const float* gamma = (const float*)d_in[17];
    const float* beta  = (const float*)d_in[18];
    const float* ew1 = (const float*)d_in[19];
    const float* eb1 = (const float*)d_in[20];
    const float* ew2 = (const float*)d_in[21];
    const float* eb2 = (const float*)d_in[22];
    const float* hw1 = (const float*)d_in[23];
    const float* hb1 = (const float*)d_in[24];
    const float* hw2 = (const float*)d_in[25];
    const float* hb2 = (const float*)d_in[26];
    const float* hw3 = (const float*)d_in[27];
    const float* hb3 = (const float*)d_in[28];

    const int N = in_sizes[0] / 32;
    const int E = in_sizes[1] / 2;
    const int G = in_sizes[4] / 200;
    const float bnscale = 1.0f / sqrtf(1.0f + 1e-5f);

    float* p_h;    cudaGetSymbolAddress((void**)&p_h, g_h);
    float* p_z;    cudaGetSymbolAddress((void**)&p_z, g_z);
    float* p_etab; cudaGetSymbolAddress((void**)&p_etab, g_etab);
    float* p_ex1;  cudaGetSymbolAddress((void**)&p_ex1, g_ex1);
    float* p_ex2;  cudaGetSymbolAddress((void**)&p_ex2, g_ex2);
    float* p_comb; cudaGetSymbolAddress((void**)&p_comb, g_comb);
    float* p_o1;   cudaGetSymbolAddress((void**)&p_o1, g_o1);
    float* p_o2;   cudaGetSymbolAddress((void**)&p_o2, g_o2);

    auto kNode  = mlp2_kernel<32, false>;
    auto kLayer = mlp2_kernel<128, true>;
    cudaFuncSetAttribute((const void*)kNode,  cudaFuncAttributeMaxDynamicSharedMemorySize, 131072);
    cudaFuncSetAttribute((const void*)kLayer, cudaFuncAttributeMaxDynamicSharedMemorySize, 131072);

    const int nb = (N + 127) / 128;

    // node projection MLP -> g_h
    kNode<<<nb, 256, 131072>>>(x, N, nw1, nb1, nw2, nb2, nullptr, nullptr, 1.f, p_h);
    // edge type tables (all layers)
    etab_kernel<<<LLAYERS * 24, 128>>>(te, de, lew, leb);

    const int n4 = N * 32;
    for (int l = 0; l < LLAYERS; l++) {
        copy_kernel<<<(n4 + 255) / 256, 256>>>(p_h, p_z, n4);
        msg_kernel<<<(E + 7) / 8, 256>>>(ei, ea, p_etab + l * 24 * 128, E, p_h, p_z);
        kLayer<<<nb, 256, 131072>>>(p_z, N,
                                    mw1 + (size_t)l * 128 * 128, mb1 + l * 128,
                                    mw2 + (size_t)l * 128 * 128, mb2 + l * 128,
                                    gamma + l * 128, beta + l * 128, bnscale, p_h);
    }

    float* out_f    = (float*)d_out;
    float* out_ge   = out_f + G;              // graph_emb [G,256]
    float* out_comb = out_f + G + G * 256;    // combined  [G,384]

    pool_init_kernel<<<(G * 128 + 255) / 256, 256>>>(G);
    pool_kernel<<<(N * 32 + 255) / 256, 256>>>(p_h, batch, N);
    pool_fin_kernel<<<(G * 128 + 255) / 256, 256>>>(G, out_ge);

    dense_relu_kernel<<<(G * 128 + 255) / 256, 256>>>(expf_, ew1, eb1, p_ex1, G, 200, 128);
    dense_relu_kernel<<<(G * 128 + 255) / 256, 256>>>(p_ex1, ew2, eb2, p_ex2, G, 128, 128);
    comb_kernel<<<(G * 384 + 255) / 256, 256>>>(G, out_comb);
    dense_relu_kernel<<<(G * 256 + 255) / 256, 256>>>(p_comb, hw1, hb1, p_o1, G, 384, 256);
    dense_relu_kernel<<<(G * 128 + 255) / 256, 256>>>(p_o1, hw2, hb2, p_o2, G, 256, 128);
    head3_kernel<<<(G + 127) / 128, 128>>>(G, hw3, hb3, out_f);
}

// round 3
// speedup vs baseline: 1.3843x; 1.3843x over previous
#include <cuda_runtime.h>
#include <math.h>

#define HDIM 128
#define LLAYERS 5
#define NMAX 100000
#define EMAX 200000
#define GMAX 2000

// ---------------- scratch (static device globals; no allocation) ----------------
__device__ float    g_h[NMAX * HDIM];
__device__ float    g_z[NMAX * HDIM];
__device__ float    g_etab[LLAYERS * 24 * HDIM];
__device__ __align__(16) unsigned g_wfrag[368640];   // tf32 big/small weight fragments
__device__ float    g_msum[GMAX * HDIM];
__device__ unsigned g_mmax[GMAX * HDIM];
__device__ int      g_cnt[GMAX];
__device__ float    g_gemb[GMAX * 256];
__device__ float    g_ex1[GMAX * HDIM];
__device__ float    g_ex2[GMAX * HDIM];
__device__ float    g_comb[GMAX * 384];
__device__ float    g_o1[GMAX * 256];
__device__ float    g_o2[GMAX * 128];

// ---------------- helpers ----------------
__device__ __forceinline__ unsigned encf(float f) {
    unsigned u = __float_as_uint(f);
    return (u & 0x80000000u) ? ~u : (u | 0x80000000u);
}
__device__ __forceinline__ float decf(unsigned u) {
    return (u & 0x80000000u) ? __uint_as_float(u & 0x7FFFFFFFu) : __uint_as_float(~u);
}
__device__ __forceinline__ unsigned f2tf32(float f) {
    unsigned u;
    asm("cvt.rna.tf32.f32 %0, %1;" : "=r"(u) : "f"(f));
    return u;
}
__device__ __forceinline__ void mma_tf32(float c[4], const unsigned a[4],
                                         unsigned b0, unsigned b1) {
    asm volatile(
        "mma.sync.aligned.m16n8k8.row.col.f32.tf32.tf32.f32 "
        "{%0,%1,%2,%3}, {%4,%5,%6,%7}, {%8,%9}, {%0,%1,%2,%3};"
        : "+f"(c[0]), "+f"(c[1]), "+f"(c[2]), "+f"(c[3])
        : "r"(a[0]), "r"(a[1]), "r"(a[2]), "r"(a[3]), "r"(b0), "r"(b1));
}

// ---------------- weight fragment precompute (tf32 big/small split) -------------
// W: [K,128] row-major. out layout: [kstep][ntile][lane][4] = {bb0, bb1, bs0, bs1}
__global__ void wfrag_kernel(const float* __restrict__ W, unsigned* __restrict__ out)
{
    int ks = blockIdx.x, nt = blockIdx.y, lane = threadIdx.x;
    int k = ks * 8 + (lane & 3);
    int n = nt * 8 + (lane >> 2);
    float w0 = W[k * 128 + n];
    float w1 = W[(k + 4) * 128 + n];
    unsigned bb0 = f2tf32(w0);
    unsigned bs0 = f2tf32(w0 - __uint_as_float(bb0));
    unsigned bb1 = f2tf32(w1);
    unsigned bs1 = f2tf32(w1 - __uint_as_float(bb1));
    unsigned* p = out + ((size_t)(ks * 16 + nt) * 32 + lane) * 4;
    p[0] = bb0; p[1] = bb1; p[2] = bs0; p[3] = bs1;
}

// ---------------- 3xTF32 tile GEMM: acc += As_tile @ W(frag) ----------------
// As: smem fp32 tile, row stride = stride (stride ≡ K+4 pattern → conflict-free)
template <int K>
__device__ __forceinline__ void gemm_tile(const float* As, int stride,
                                          const unsigned* __restrict__ frag,
                                          int rowgrp, int colgrp, int lane,
                                          float acc[2][8][4])
{
    #pragma unroll 4
    for (int ks = 0; ks < K / 8; ks++) {
        int k0 = ks * 8;
        unsigned ab[2][4], al[2][4];
        #pragma unroll
        for (int mt = 0; mt < 2; mt++) {
            int r0 = rowgrp * 32 + mt * 16 + (lane >> 2);
            int c0 = k0 + (lane & 3);
            #pragma unroll
            for (int i = 0; i < 4; i++) {
                int r = r0 + 8 * (i & 1);
                int c = c0 + 4 * (i >> 1);
                float v = As[r * stride + c];
                unsigned b = f2tf32(v);
                ab[mt][i] = b;
                al[mt][i] = f2tf32(v - __uint_as_float(b));
            }
        }
        #pragma unroll
        for (int t = 0; t < 8; t++) {
            int nt = colgrp * 8 + t;
            const uint4 bf = *(const uint4*)(frag + ((size_t)(ks * 16 + nt) * 32 + lane) * 4);
            #pragma unroll
            for (int mt = 0; mt < 2; mt++) {
                mma_tf32(acc[mt][t], ab[mt], bf.x, bf.y);   // Ab*Bb
                mma_tf32(acc[mt][t], ab[mt], bf.z, bf.w);   // Ab*Bs
                mma_tf32(acc[mt][t], al[mt], bf.x, bf.y);   // As*Bb
            }
        }
    }
}

// ---------------- fused 2-GEMM MLP on tensor cores ----------------
// LAYER=true : A_in = A + Aadd; H[r] += relu(bn(mlp(A_in)))   (residual, in place)
// LAYER=false: H[r] = mlp(A)
template <int K1, bool LAYER>
__global__ __launch_bounds__(256, 2)
void mlp2_mma_kernel(const float* A, const float* __restrict__ Aadd, int N,
                     const unsigned* __restrict__ frag1, const float* __restrict__ b1,
                     const unsigned* __restrict__ frag2, const float* __restrict__ b2,
                     const float* __restrict__ gamma, const float* __restrict__ beta,
                     float bnscale, float* H)
{
    extern __shared__ float As[];  // 128 x 132 fp32 max
    const int tid = threadIdx.x, lane = tid & 31, warp = tid >> 5;
    const int rowgrp = warp >> 1, colgrp = warp & 1;
    const int n0 = blockIdx.x * 128;
    const int S1 = K1 + 4;

    // load A tile [128 x K1] (zero-padded rows beyond N)
    {
        const int QK = K1 / 4;
        #pragma unroll
        for (int i = 0; i < (128 * QK) / 256; i++) {
            int idx = tid + i * 256;
            int r = idx / QK, cq = idx % QK;
            float4 v = make_float4(0.f, 0.f, 0.f, 0.f);
            if (n0 + r < N) {
                v = *(const float4*)(A + (size_t)(n0 + r) * K1 + cq * 4);
                if (LAYER) {
                    float4 w = *(const float4*)(Aadd + (size_t)(n0 + r) * K1 + cq * 4);
                    v.x += w.x; v.y += w.y; v.z += w.z; v.w += w.w;
                }
            }
            *(float4*)(As + r * S1 + cq * 4) = v;
        }
    }
    __syncthreads();

    float acc[2][8][4];
    #pragma unroll
    for (int mt = 0; mt < 2; mt++)
        #pragma unroll
        for (int t = 0; t < 8; t++)
            #pragma unroll
            for (int j = 0; j < 4; j++) acc[mt][t][j] = 0.f;

    gemm_tile<K1>(As, S1, frag1, rowgrp, colgrp, lane, acc);
    __syncthreads();

    // intermediate: relu(acc + b1) -> As (stride 132)
    #pragma unroll
    for (int mt = 0; mt < 2; mt++) {
        #pragma unroll
        for (int t = 0; t < 8; t++) {
            int col = (colgrp * 8 + t) * 8 + 2 * (lane & 3);
            float bb0 = __ldg(b1 + col), bb1 = __ldg(b1 + col + 1);
            int r0 = rowgrp * 32 + mt * 16 + (lane >> 2);
            As[r0 * 132 + col]           = fmaxf(acc[mt][t][0] + bb0, 0.f);
            As[r0 * 132 + col + 1]       = fmaxf(acc[mt][t][1] + bb1, 0.f);
            As[(r0 + 8) * 132 + col]     = fmaxf(acc[mt][t][2] + bb0, 0.f);
            As[(r0 + 8) * 132 + col + 1] = fmaxf(acc[mt][t][3] + bb1, 0.f);
        }
    }
    __syncthreads();

    #pragma unroll
    for (int mt = 0; mt < 2; mt++)
        #pragma unroll
        for (int t = 0; t < 8; t++)
            #pragma unroll
            for (int j = 0; j < 4; j++) acc[mt][t][j] = 0.f;

    gemm_tile<128>(As, 132, frag2, rowgrp, colgrp, lane, acc);

    // epilogue
    #pragma unroll
    for (int mt = 0; mt < 2; mt++) {
        #pragma unroll
        for (int t = 0; t < 8; t++) {
            int col = (colgrp * 8 + t) * 8 + 2 * (lane & 3);
            float bb0 = __ldg(b2 + col), bb1 = __ldg(b2 + col + 1);
            int r0 = rowgrp * 32 + mt * 16 + (lane >> 2);
            if (LAYER) {
                float gm0 = __ldg(gamma + col) * bnscale, gm1 = __ldg(gamma + col + 1) * bnscale;
                float bt0 = __ldg(beta + col), bt1 = __ldg(beta + col + 1);
                #pragma unroll
                for (int half = 0; half < 2; half++) {
                    int row = n0 + r0 + 8 * half;
                    if (row < N) {
                        float z0 = fmaxf((acc[mt][t][2 * half + 0] + bb0) * gm0 + bt0, 0.f);
                        float z1 = fmaxf((acc[mt][t][2 * half + 1] + bb1) * gm1 + bt1, 0.f);
                        float* hp = H + (size_t)row * 128 + col;
                        float2 hv = *(float2*)hp;     // h_in (residual)
                        hv.x += z0; hv.y += z1;
                        *(float2*)hp = hv;
                    }
                }
            } else {
                #pragma unroll
                for (int half = 0; half < 2; half++) {
                    int row = n0 + r0 + 8 * half;
                    if (row < N) {
                        float2 o;
                        o.x = acc[mt][t][2 * half + 0] + bb0;
                        o.y = acc[mt][t][2 * half + 1] + bb1;
                        *(float2*)(H + (size_t)row * 128 + col) = o;
                    }
                }
            }
        }
    }
}

// ---------------- edge-type table: etab[l][t] = (te[bt]+de[bd]) @ lew[l] + leb[l] --
__global__ void etab_kernel(const float* __restrict__ te, const float* __restrict__ de,
                            const float* __restrict__ lew, const float* __restrict__ leb)
{
    int l = blockIdx.x / 24, t = blockIdx.x % 24;
    int bt = t / 4, bd = t % 4;
    int c = threadIdx.x;
    float s = leb[l * 128 + c];
    #pragma unroll 4
    for (int k = 0; k < 64; k++) {
        float ev = te[bt * 64 + k] + de[bd * 64 + k];
        s += ev * __ldg(lew + (size_t)(l * 64 + k) * 128 + c);
    }
    g_etab[(l * 24 + t) * 128 + c] = s;
}

// ---------------- zero-fill (aggr buffer) ----------------
__global__ void zero_kernel(float* __restrict__ dst, int n4)
{
    int idx = blockIdx.x * blockDim.x + threadIdx.x;
    if (idx < n4) ((float4*)dst)[idx] = make_float4(0.f, 0.f, 0.f, 0.f);
}

// ---------------- message + scatter: z[dst] += relu(h[src] + etab[type]) ----------
__global__ void msg_kernel(const int* __restrict__ ei, const int* __restrict__ ea,
                           const float* __restrict__ etab_l, int E,
                           const float* __restrict__ h, float* __restrict__ z)
{
    int e = blockIdx.x * 8 + (threadIdx.x >> 5);
    if (e >= E) return;
    int lane = threadIdx.x & 31;
    int src = ei[e], dst = ei[E + e];
    int bt = ea[2 * e], bd = ea[2 * e + 1];
    bt = min(max(bt, 0), 5);
    bd = min(max(bd, 0), 3);
    const float* et = etab_l + (bt * 4 + bd) * 128;
    float4 hv = *(const float4*)(h + (size_t)src * 128 + lane * 4);
    float4 ev = *(const float4*)(et + lane * 4);
    float m0 = fmaxf(hv.x + ev.x, 0.f);
    float m1 = fmaxf(hv.y + ev.y, 0.f);
    float m2 = fmaxf(hv.z + ev.z, 0.f);
    float m3 = fmaxf(hv.w + ev.w, 0.f);
    float* zp = z + (size_t)dst * 128 + lane * 4;
    atomicAdd(zp + 0, m0);
    atomicAdd(zp + 1, m1);
    atomicAdd(zp + 2, m2);
    atomicAdd(zp + 3, m3);
}

// ---------------- pooling ----------------
__global__ void pool_init_kernel(int G)
{
    int idx = blockIdx.x * blockDim.x + threadIdx.x;
    if (idx < G * 128) { g_msum[idx] = 0.f; g_mmax[idx] = 0u; }
    if (idx < G) g_cnt[idx] = 0;
}

__global__ void pool_kernel(const float* __restrict__ h, const int* __restrict__ batch, int N)
{
    int idx = blockIdx.x * blockDim.x + threadIdx.x;
    if (idx >= N * 32) return;
    int n = idx >> 5, c4 = idx & 31;
    int g = __ldg(batch + n);
    float4 v = *(const float4*)(h + (size_t)n * 128 + c4 * 4);
    float* ms = &g_msum[g * 128 + c4 * 4];
    atomicAdd(ms + 0, v.x); atomicAdd(ms + 1, v.y);
    atomicAdd(ms + 2, v.z); atomicAdd(ms + 3, v.w);
    unsigned* mm = &g_mmax[g * 128 + c4 * 4];
    atomicMax(mm + 0, encf(v.x)); atomicMax(mm + 1, encf(v.y));
    atomicMax(mm + 2, encf(v.z)); atomicMax(mm + 3, encf(v.w));
    if (c4 == 0) atomicAdd(&g_cnt[g], 1);
}

__global__ void pool_fin_kernel(int G, float* __restrict__ out_ge)
{
    int idx = blockIdx.x * blockDim.x + threadIdx.x;
    if (idx >= G * 128) return;
    int g = idx / 128, c = idx % 128;
    float mean = g_msum[idx] / (float)g_cnt[g];
    float mx = decf(g_mmax[idx]);
    g_gemb[g * 256 + c] = mean;
    g_gemb[g * 256 + 128 + c] = mx;
    out_ge[g * 256 + c] = mean;
    out_ge[g * 256 + 128 + c] = mx;
}

// ---------------- small dense layers (naive, tiny G) ----------------
__global__ void dense_relu_kernel(const float* __restrict__ X, const float* __restrict__ W,
                                  const float* __restrict__ b, float* __restrict__ Y,
                                  int G, int K, int C)
{
    int idx = blockIdx.x * blockDim.x + threadIdx.x;
    if (idx >= G * C) return;
    int g = idx / C, c = idx % C;
    float s = __ldg(b + c);
    #pragma unroll 4
    for (int k = 0; k < K; k++)
        s += __ldg(X + (size_t)g * K + k) * __ldg(W + (size_t)k * C + c);
    Y[idx] = fmaxf(s, 0.f);
}

__global__ void comb_kernel(int G, float* __restrict__ out_comb)
{
    int idx = blockIdx.x * blockDim.x + threadIdx.x;
    if (idx >= G * 384) return;
    int g = idx / 384, c = idx % 384;
    float v = (c < 256) ? g_gemb[g * 256 + c] : g_ex2[g * 128 + (c - 256)];
    g_comb[idx] = v;
    out_comb[idx] = v;
}

__global__ void head3_kernel(int G, const float* __restrict__ hw3,
                             const float* __restrict__ hb3, float* __restrict__ out)
{
    int g = blockIdx.x * blockDim.x + threadIdx.x;
    if (g >= G) return;
    float s = __ldg(hb3);
    #pragma unroll 4
    for (int k = 0; k < 128; k++)
        s += g_o2[g * 128 + k] * __ldg(hw3 + k);
    out[g] = s;
}

// ---------------- launch ----------------
extern "C" void kernel_launch(void* const* d_in, const int* in_sizes, int n_in,
                              void* d_out, int out_size)
{
    const float* x     = (const float*)d_in[0];
    const int*   ei    = (const int*)d_in[1];
    const int*   ea    = (const int*)d_in[2];
    const int*   batch = (const int*)d_in[3];
    const float* expf_ = (const float*)d_in[4];
    const float* nw1 = (const float*)d_in[5];
    const float* nb1 = (const float*)d_in[6];
    const float* nw2 = (const float*)d_in[7];
    const float* nb2 = (const float*)d_in[8];
    const float* te  = (const float*)d_in[9];
    const float* de  = (const float*)d_in[10];
    const float* lew = (const float*)d_in[11];
    const float* leb = (const float*)d_in[12];
    const float* mw1 = (const float*)d_in[13];
    const float* mb1 = (const float*)d_in[14];
    const float* mw2 = (const float*)d_in[15];
    const float* mb2 = (const float*)d_in[16];
    const float* gamma = (const float*)d_in[17];
    const float* beta  = (const float*)d_in[18];
    const float* ew1 = (const float*)d_in[19];
    const float* eb1 = (const float*)d_in[20];
    const float* ew2 = (const float*)d_in[21];
    const float* eb2 = (const float*)d_in[22];
    const float* hw1 = (const float*)d_in[23];
    const float* hb1 = (const float*)d_in[24];
    const float* hw2 = (const float*)d_in[25];
    const float* hb2 = (const float*)d_in[26];
    const float* hw3 = (const float*)d_in[27];
    const float* hb3 = (const float*)d_in[28];

    const int N = in_sizes[0] / 32;
    const int E = in_sizes[1] / 2;
    const int G = in_sizes[4] / 200;
    const float bnscale = 1.0f / sqrtf(1.0f + 1e-5f);

    float*    p_h;     cudaGetSymbolAddress((void**)&p_h, g_h);
    float*    p_z;     cudaGetSymbolAddress((void**)&p_z, g_z);
    float*    p_etab;  cudaGetSymbolAddress((void**)&p_etab, g_etab);
    unsigned* p_wf;    cudaGetSymbolAddress((void**)&p_wf, g_wfrag);
    float*    p_ex1;   cudaGetSymbolAddress((void**)&p_ex1, g_ex1);
    float*    p_ex2;   cudaGetSymbolAddress((void**)&p_ex2, g_ex2);
    float*    p_comb;  cudaGetSymbolAddress((void**)&p_comb, g_comb);
    float*    p_o1;    cudaGetSymbolAddress((void**)&p_o1, g_o1);
    float*    p_o2;    cudaGetSymbolAddress((void**)&p_o2, g_o2);

    // fragment buffer offsets (in u32): node1 @0 (4 ksteps), node2 @8192,
    // then per-layer mw1/mw2 (16 ksteps = 32768 u32 each)
    const size_t OFF_N1 = 0;
    const size_t OFF_N2 = 8192;
    const size_t BASE_L = 40960;
    const size_t SZ128  = 32768;

    // 1) build weight fragment tables (tf32 big/small split)
    wfrag_kernel<<<dim3(4, 16), 32>>>(nw1, p_wf + OFF_N1);
    wfrag_kernel<<<dim3(16, 16), 32>>>(nw2, p_wf + OFF_N2);
    for (int l = 0; l < LLAYERS; l++) {
        wfrag_kernel<<<dim3(16, 16), 32>>>(mw1 + (size_t)l * 128 * 128,
                                           p_wf + BASE_L + (size_t)(2 * l) * SZ128);
        wfrag_kernel<<<dim3(16, 16), 32>>>(mw2 + (size_t)l * 128 * 128,
                                           p_wf + BASE_L + (size_t)(2 * l + 1) * SZ128);
    }
    // 2) edge type tables
    etab_kernel<<<LLAYERS * 24, 128>>>(te, de, lew, leb);

    auto kNode  = mlp2_mma_kernel<32, false>;
    auto kLayer = mlp2_mma_kernel<128, true>;
    cudaFuncSetAttribute((const void*)kNode,  cudaFuncAttributeMaxDynamicSharedMemorySize, 67584);
    cudaFuncSetAttribute((const void*)kLayer, cudaFuncAttributeMaxDynamicSharedMemorySize, 67584);

    const int nb = (N + 127) / 128;
    const int n4 = N * 32;

    // 3) node projection MLP -> g_h
    kNode<<<nb, 256, 67584>>>(x, nullptr, N, p_wf + OFF_N1, nb1, p_wf + OFF_N2, nb2,
                              nullptr, nullptr, 1.f, p_h);

    // 4) GINE layers
    for (int l = 0; l < LLAYERS; l++) {
        zero_kernel<<<(n4 + 255) / 256, 256>>>(p_z, n4);
        msg_kernel<<<(E + 7) / 8, 256>>>(ei, ea, p_etab + (size_t)l * 24 * 128, E, p_h, p_z);
        kLayer<<<nb, 256, 67584>>>(p_h, p_z, N,
                                   p_wf + BASE_L + (size_t)(2 * l) * SZ128, mb1 + l * 128,
                                   p_wf + BASE_L + (size_t)(2 * l + 1) * SZ128, mb2 + l * 128,
                                   gamma + l * 128, beta + l * 128, bnscale, p_h);
    }

    // 5) readout + heads
    float* out_f    = (float*)d_out;
    float* out_ge   = out_f + G;              // graph_emb [G,256]
    float* out_comb = out_f + G + G * 256;    // combined  [G,384]

    pool_init_kernel<<<(G * 128 + 255) / 256, 256>>>(G);
    pool_kernel<<<(N * 32 + 255) / 256, 256>>>(p_h, batch, N);
    pool_fin_kernel<<<(G * 128 + 255) / 256, 256>>>(G, out_ge);

    dense_relu_kernel<<<(G * 128 + 255) / 256, 256>>>(expf_, ew1, eb1, p_ex1, G, 200, 128);
    dense_relu_kernel<<<(G * 128 + 255) / 256, 256>>>(p_ex1, ew2, eb2, p_ex2, G, 128, 128);
    comb_kernel<<<(G * 384 + 255) / 256, 256>>>(G, out_comb);
    dense_relu_kernel<<<(G * 256 + 255) / 256, 256>>>(p_comb, hw1, hb1, p_o1, G, 384, 256);
    dense_relu_kernel<<<(G * 128 + 255) / 256, 256>>>(p_o1, hw2, hb2, p_o2, G, 256, 128);
    head3_kernel<<<(G + 127) / 128, 128>>>(G, hw3, hb3, out_f);
}

// round 4
// speedup vs baseline: 2.0484x; 1.4797x over previous
#include <cuda_runtime.h>
#include <math.h>

#define HDIM 128
#define LLAYERS 5
#define NMAX 100000
#define EMAX 200000
#define GMAX 2000

// ---------------- scratch (static device globals; no allocation) ----------------
__device__ float    g_h[NMAX * HDIM];
__device__ float    g_z[NMAX * HDIM];
__device__ float    g_etab[LLAYERS * 24 * HDIM];
__device__ __align__(16) unsigned g_wfrag[368640];   // bf16 hi/lo weight fragments
__device__ float    g_gemb[GMAX * 256];
__device__ float    g_ex1[GMAX * HDIM];
__device__ float    g_ex2[GMAX * HDIM];
__device__ float    g_comb[GMAX * 384];
__device__ float    g_o1[GMAX * 256];
__device__ float    g_o2[GMAX * 128];

// ---------------- helpers ----------------
__device__ __forceinline__ void bf16_split2(float x, float y, unsigned& hi, unsigned& lo) {
    // hi = pack(bf16(y), bf16(x)) : x in low half, y in high half
    asm("cvt.rn.bf16x2.f32 %0, %1, %2;" : "=r"(hi) : "f"(y), "f"(x));
    float hx = __uint_as_float(hi << 16);
    float hy = __uint_as_float(hi & 0xffff0000u);
    float lx = x - hx, ly = y - hy;
    asm("cvt.rn.bf16x2.f32 %0, %1, %2;" : "=r"(lo) : "f"(ly), "f"(lx));
}
__device__ __forceinline__ void mma_bf16(float c[4], const unsigned a[4],
                                         unsigned b0, unsigned b1) {
    asm volatile(
        "mma.sync.aligned.m16n8k16.row.col.f32.bf16.bf16.f32 "
        "{%0,%1,%2,%3}, {%4,%5,%6,%7}, {%8,%9}, {%0,%1,%2,%3};"
        : "+f"(c[0]), "+f"(c[1]), "+f"(c[2]), "+f"(c[3])
        : "r"(a[0]), "r"(a[1]), "r"(a[2]), "r"(a[3]), "r"(b0), "r"(b1));
}

// ---------------- weight fragment precompute (bf16 hi/lo split) -------------
// W: [K,128] row-major. out[(ks16*16 + ntile)*32 + lane] = uint4{bhi0,bhi1,blo0,blo1}
__global__ void wfrag_kernel(const float* __restrict__ W, unsigned* __restrict__ out)
{
    int ks = blockIdx.x, nt = blockIdx.y, lane = threadIdx.x;
    int n  = nt * 8 + (lane >> 2);
    int k0 = ks * 16 + (lane & 3) * 2;
    float w00 = W[k0 * 128 + n];
    float w01 = W[(k0 + 1) * 128 + n];
    float w10 = W[(k0 + 8) * 128 + n];
    float w11 = W[(k0 + 9) * 128 + n];
    unsigned bh0, bl0, bh1, bl1;
    bf16_split2(w00, w01, bh0, bl0);
    bf16_split2(w10, w11, bh1, bl1);
    unsigned* p = out + ((size_t)(ks * 16 + nt) * 32 + lane) * 4;
    p[0] = bh0; p[1] = bh1; p[2] = bl0; p[3] = bl1;
}

// ---------------- 3x-bf16 tile GEMM: acc += As_tile @ W(frag) ----------------
template <int K>
__device__ __forceinline__ void gemm_tile(const float* As, int stride,
                                          const unsigned* __restrict__ frag,
                                          int rowgrp, int colgrp, int lane,
                                          float acc[2][8][4])
{
    #pragma unroll 4
    for (int ks = 0; ks < K / 16; ks++) {
        int k0 = ks * 16 + (lane & 3) * 2;
        unsigned ahi[2][4], alo[2][4];
        #pragma unroll
        for (int mt = 0; mt < 2; mt++) {
            int r0 = rowgrp * 32 + mt * 16 + (lane >> 2);
            float2 v00 = *(const float2*)(As + r0 * stride + k0);
            float2 v10 = *(const float2*)(As + (r0 + 8) * stride + k0);
            float2 v01 = *(const float2*)(As + r0 * stride + k0 + 8);
            float2 v11 = *(const float2*)(As + (r0 + 8) * stride + k0 + 8);
            bf16_split2(v00.x, v00.y, ahi[mt][0], alo[mt][0]);
            bf16_split2(v10.x, v10.y, ahi[mt][1], alo[mt][1]);
            bf16_split2(v01.x, v01.y, ahi[mt][2], alo[mt][2]);
            bf16_split2(v11.x, v11.y, ahi[mt][3], alo[mt][3]);
        }
        #pragma unroll
        for (int t = 0; t < 8; t++) {
            int nt = colgrp * 8 + t;
            const uint4 bf = *(const uint4*)(frag + ((size_t)(ks * 16 + nt) * 32 + lane) * 4);
            #pragma unroll
            for (int mt = 0; mt < 2; mt++) {
                mma_bf16(acc[mt][t], ahi[mt], bf.x, bf.y);   // hi*hi
                mma_bf16(acc[mt][t], ahi[mt], bf.z, bf.w);   // hi*lo
                mma_bf16(acc[mt][t], alo[mt], bf.x, bf.y);   // lo*hi
            }
        }
    }
}

// ---------------- fused 2-GEMM MLP on tensor cores ----------------
// LAYER=true : A_in = A + Aadd; H[r] += relu(bn(mlp(A_in)))   (residual, in place)
// LAYER=false: H[r] = mlp(A)
template <int K1, bool LAYER>
__global__ __launch_bounds__(256, 2)
void mlp2_mma_kernel(const float* A, const float* __restrict__ Aadd, int N,
                     const unsigned* __restrict__ frag1, const float* __restrict__ b1,
                     const unsigned* __restrict__ frag2, const float* __restrict__ b2,
                     const float* __restrict__ gamma, const float* __restrict__ beta,
                     float bnscale, float* H)
{
    extern __shared__ float As[];  // 128 x 132 fp32 max
    const int tid = threadIdx.x, lane = tid & 31, warp = tid >> 5;
    const int rowgrp = warp >> 1, colgrp = warp & 1;
    const int n0 = blockIdx.x * 128;
    const int S1 = K1 + 4;

    // load A tile [128 x K1] (zero-padded rows beyond N)
    {
        const int QK = K1 / 4;
        #pragma unroll
        for (int i = 0; i < (128 * QK) / 256; i++) {
            int idx = tid + i * 256;
            int r = idx / QK, cq = idx % QK;
            float4 v = make_float4(0.f, 0.f, 0.f, 0.f);
            if (n0 + r < N) {
                v = *(const float4*)(A + (size_t)(n0 + r) * K1 + cq * 4);
                if (LAYER) {
                    float4 w = *(const float4*)(Aadd + (size_t)(n0 + r) * K1 + cq * 4);
                    v.x += w.x; v.y += w.y; v.z += w.z; v.w += w.w;
                }
            }
            *(float4*)(As + r * S1 + cq * 4) = v;
        }
    }
    __syncthreads();

    float acc[2][8][4];
    #pragma unroll
    for (int mt = 0; mt < 2; mt++)
        #pragma unroll
        for (int t = 0; t < 8; t++)
            #pragma unroll
            for (int j = 0; j < 4; j++) acc[mt][t][j] = 0.f;

    gemm_tile<K1>(As, S1, frag1, rowgrp, colgrp, lane, acc);
    __syncthreads();

    // intermediate: relu(acc + b1) -> As (stride 132)
    #pragma unroll
    for (int mt = 0; mt < 2; mt++) {
        #pragma unroll
        for (int t = 0; t < 8; t++) {
            int col = (colgrp * 8 + t) * 8 + 2 * (lane & 3);
            float bb0 = __ldg(b1 + col), bb1 = __ldg(b1 + col + 1);
            int r0 = rowgrp * 32 + mt * 16 + (lane >> 2);
            As[r0 * 132 + col]           = fmaxf(acc[mt][t][0] + bb0, 0.f);
            As[r0 * 132 + col + 1]       = fmaxf(acc[mt][t][1] + bb1, 0.f);
            As[(r0 + 8) * 132 + col]     = fmaxf(acc[mt][t][2] + bb0, 0.f);
            As[(r0 + 8) * 132 + col + 1] = fmaxf(acc[mt][t][3] + bb1, 0.f);
        }
    }
    __syncthreads();

    #pragma unroll
    for (int mt = 0; mt < 2; mt++)
        #pragma unroll
        for (int t = 0; t < 8; t++)
            #pragma unroll
            for (int j = 0; j < 4; j++) acc[mt][t][j] = 0.f;

    gemm_tile<128>(As, 132, frag2, rowgrp, colgrp, lane, acc);

    // epilogue
    #pragma unroll
    for (int mt = 0; mt < 2; mt++) {
        #pragma unroll
        for (int t = 0; t < 8; t++) {
            int col = (colgrp * 8 + t) * 8 + 2 * (lane & 3);
            float bb0 = __ldg(b2 + col), bb1 = __ldg(b2 + col + 1);
            int r0 = rowgrp * 32 + mt * 16 + (lane >> 2);
            if (LAYER) {
                float gm0 = __ldg(gamma + col) * bnscale, gm1 = __ldg(gamma + col + 1) * bnscale;
                float bt0 = __ldg(beta + col), bt1 = __ldg(beta + col + 1);
                #pragma unroll
                for (int half = 0; half < 2; half++) {
                    int row = n0 + r0 + 8 * half;
                    if (row < N) {
                        float z0 = fmaxf((acc[mt][t][2 * half + 0] + bb0) * gm0 + bt0, 0.f);
                        float z1 = fmaxf((acc[mt][t][2 * half + 1] + bb1) * gm1 + bt1, 0.f);
                        float* hp = H + (size_t)row * 128 + col;
                        float2 hv = *(float2*)hp;     // h_in (residual)
                        hv.x += z0; hv.y += z1;
                        *(float2*)hp = hv;
                    }
                }
            } else {
                #pragma unroll
                for (int half = 0; half < 2; half++) {
                    int row = n0 + r0 + 8 * half;
                    if (row < N) {
                        float2 o;
                        o.x = acc[mt][t][2 * half + 0] + bb0;
                        o.y = acc[mt][t][2 * half + 1] + bb1;
                        *(float2*)(H + (size_t)row * 128 + col) = o;
                    }
                }
            }
        }
    }
}

// ---------------- edge-type table: etab[l][t] = (te[bt]+de[bd]) @ lew[l] + leb[l] --
__global__ void etab_kernel(const float* __restrict__ te, const float* __restrict__ de,
                            const float* __restrict__ lew, const float* __restrict__ leb)
{
    int l = blockIdx.x / 24, t = blockIdx.x % 24;
    int bt = t / 4, bd = t % 4;
    int c = threadIdx.x;
    float s = leb[l * 128 + c];
    #pragma unroll 4
    for (int k = 0; k < 64; k++) {
        float ev = te[bt * 64 + k] + de[bd * 64 + k];
        s += ev * __ldg(lew + (size_t)(l * 64 + k) * 128 + c);
    }
    g_etab[(l * 24 + t) * 128 + c] = s;
}

// ---------------- zero-fill (aggr buffer) ----------------
__global__ void zero_kernel(float* __restrict__ dst, int n4)
{
    int idx = blockIdx.x * blockDim.x + threadIdx.x;
    if (idx < n4) ((float4*)dst)[idx] = make_float4(0.f, 0.f, 0.f, 0.f);
}

// ---------------- message + scatter: z[dst] += relu(h[src] + etab[type]) ----------
__global__ void msg_kernel(const int* __restrict__ ei, const int* __restrict__ ea,
                           const float* __restrict__ etab_l, int E,
                           const float* __restrict__ h, float* __restrict__ z)
{
    int e = blockIdx.x * 8 + (threadIdx.x >> 5);
    if (e >= E) return;
    int lane = threadIdx.x & 31;
    int src = ei[e], dst = ei[E + e];
    int bt = ea[2 * e], bd = ea[2 * e + 1];
    bt = min(max(bt, 0), 5);
    bd = min(max(bd, 0), 3);
    const float* et = etab_l + (bt * 4 + bd) * 128;
    float4 hv = *(const float4*)(h + (size_t)src * 128 + lane * 4);
    float4 ev = *(const float4*)(et + lane * 4);
    float m0 = fmaxf(hv.x + ev.x, 0.f);
    float m1 = fmaxf(hv.y + ev.y, 0.f);
    float m2 = fmaxf(hv.z + ev.z, 0.f);
    float m3 = fmaxf(hv.w + ev.w, 0.f);
    float* zp = z + (size_t)dst * 128 + lane * 4;
    asm volatile("red.global.add.v4.f32 [%0], {%1,%2,%3,%4};"
                 :: "l"(zp), "f"(m0), "f"(m1), "f"(m2), "f"(m3) : "memory");
}

// ---------------- segmented pooling (batch is contiguous, npg nodes/graph) -------
__global__ void pool_seg_kernel(const float* __restrict__ h, int npg, float* __restrict__ out_ge)
{
    int g = blockIdx.x, c = threadIdx.x;
    const float* p = h + (size_t)g * npg * 128 + c;
    float s = 0.f, m = -INFINITY;
    for (int i = 0; i < npg; i++) {
        float v = p[(size_t)i * 128];
        s += v;
        m = fmaxf(m, v);
    }
    float mean = s / (float)npg;
    g_gemb[g * 256 + c] = mean;
    g_gemb[g * 256 + 128 + c] = m;
    out_ge[g * 256 + c] = mean;
    out_ge[g * 256 + 128 + c] = m;
}

// ---------------- small dense layers (naive, tiny G) ----------------
__global__ void dense_relu_kernel(const float* __restrict__ X, const float* __restrict__ W,
                                  const float* __restrict__ b, float* __restrict__ Y,
                                  int G, int K, int C)
{
    int idx = blockIdx.x * blockDim.x + threadIdx.x;
    if (idx >= G * C) return;
    int g = idx / C, c = idx % C;
    float s = __ldg(b + c);
    #pragma unroll 4
    for (int k = 0; k < K; k++)
        s += __ldg(X + (size_t)g * K + k) * __ldg(W + (size_t)k * C + c);
    Y[idx] = fmaxf(s, 0.f);
}

__global__ void comb_kernel(int G, float* __restrict__ out_comb)
{
    int idx = blockIdx.x * blockDim.x + threadIdx.x;
    if (idx >= G * 384) return;
    int g = idx / 384, c = idx % 384;
    float v = (c < 256) ? g_gemb[g * 256 + c] : g_ex2[g * 128 + (c - 256)];
    g_comb[idx] = v;
    out_comb[idx] = v;
}

__global__ void head3_kernel(int G, const float* __restrict__ hw3,
                             const float* __restrict__ hb3, float* __restrict__ out)
{
    int g = blockIdx.x * blockDim.x + threadIdx.x;
    if (g >= G) return;
    float s = __ldg(hb3);
    #pragma unroll 4
    for (int k = 0; k < 128; k++)
        s += g_o2[g * 128 + k] * __ldg(hw3 + k);
    out[g] = s;
}

// ---------------- launch ----------------
extern "C" void kernel_launch(void* const* d_in, const int* in_sizes, int n_in,
                              void* d_out, int out_size)
{
    const float* x     = (const float*)d_in[0];
    const int*   ei    = (const int*)d_in[1];
    const int*   ea    = (const int*)d_in[2];
    const float* expf_ = (const float*)d_in[4];
    const float* nw1 = (const float*)d_in[5];
    const float* nb1 = (const float*)d_in[6];
    const float* nw2 = (const float*)d_in[7];
    const float* nb2 = (const float*)d_in[8];
    const float* te  = (const float*)d_in[9];
    const float* de  = (const float*)d_in[10];
    const float* lew = (const float*)d_in[11];
    const float* leb = (const float*)d_in[12];
    const float* mw1 = (const float*)d_in[13];
    const float* mb1 = (const float*)d_in[14];
    const float* mw2 = (const float*)d_in[15];
    const float* mb2 = (const float*)d_in[16];
    const float* gamma = (const float*)d_in[17];
    const float* beta  = (const float*)d_in[18];
    const float* ew1 = (const float*)d_in[19];
    const float* eb1 = (const float*)d_in[20];
    const float* ew2 = (const float*)d_in[21];
    const float* eb2 = (const float*)d_in[22];
    const float* hw1 = (const float*)d_in[23];
    const float* hb1 = (const float*)d_in[24];
    const float* hw2 = (const float*)d_in[25];
    const float* hb2 = (const float*)d_in[26];
    const float* hw3 = (const float*)d_in[27];
    const float* hb3 = (const float*)d_in[28];

    const int N = in_sizes[0] / 32;
    const int E = in_sizes[1] / 2;
    const int G = in_sizes[4] / 200;
    const int npg = N / G;
    const float bnscale = 1.0f / sqrtf(1.0f + 1e-5f);

    float*    p_h;     cudaGetSymbolAddress((void**)&p_h, g_h);
    float*    p_z;     cudaGetSymbolAddress((void**)&p_z, g_z);
    float*    p_etab;  cudaGetSymbolAddress((void**)&p_etab, g_etab);
    unsigned* p_wf;    cudaGetSymbolAddress((void**)&p_wf, g_wfrag);
    float*    p_ex1;   cudaGetSymbolAddress((void**)&p_ex1, g_ex1);
    float*    p_ex2;   cudaGetSymbolAddress((void**)&p_ex2, g_ex2);
    float*    p_comb;  cudaGetSymbolAddress((void**)&p_comb, g_comb);
    float*    p_o1;    cudaGetSymbolAddress((void**)&p_o1, g_o1);
    float*    p_o2;    cudaGetSymbolAddress((void**)&p_o2, g_o2);

    // fragment buffer offsets (u32): node1 (K=32: 2 ks16) @0, node2 @4096,
    // per-layer mw1/mw2 (8 ks16 = 16384 u32 each) from 20480
    const size_t OFF_N1 = 0;
    const size_t OFF_N2 = 4096;
    const size_t BASE_L = 20480;
    const size_t SZ128  = 16384;

    // 1) build weight fragment tables (bf16 hi/lo split)
    wfrag_kernel<<<dim3(2, 16), 32>>>(nw1, p_wf + OFF_N1);
    wfrag_kernel<<<dim3(8, 16), 32>>>(nw2, p_wf + OFF_N2);
    for (int l = 0; l < LLAYERS; l++) {
        wfrag_kernel<<<dim3(8, 16), 32>>>(mw1 + (size_t)l * 128 * 128,
                                          p_wf + BASE_L + (size_t)(2 * l) * SZ128);
        wfrag_kernel<<<dim3(8, 16), 32>>>(mw2 + (size_t)l * 128 * 128,
                                          p_wf + BASE_L + (size_t)(2 * l + 1) * SZ128);
    }
    // 2) edge type tables
    etab_kernel<<<LLAYERS * 24, 128>>>(te, de, lew, leb);

    auto kNode  = mlp2_mma_kernel<32, false>;
    auto kLayer = mlp2_mma_kernel<128, true>;
    cudaFuncSetAttribute((const void*)kNode,  cudaFuncAttributeMaxDynamicSharedMemorySize, 67584);
    cudaFuncSetAttribute((const void*)kLayer, cudaFuncAttributeMaxDynamicSharedMemorySize, 67584);

    const int nb = (N + 127) / 128;
    const int n4 = N * 32;

    // 3) node projection MLP -> g_h
    kNode<<<nb, 256, 67584>>>(x, nullptr, N, p_wf + OFF_N1, nb1, p_wf + OFF_N2, nb2,
                              nullptr, nullptr, 1.f, p_h);

    // 4) GINE layers
    for (int l = 0; l < LLAYERS; l++) {
        zero_kernel<<<(n4 + 255) / 256, 256>>>(p_z, n4);
        msg_kernel<<<(E + 7) / 8, 256>>>(ei, ea, p_etab + (size_t)l * 24 * 128, E, p_h, p_z);
        kLayer<<<nb, 256, 67584>>>(p_h, p_z, N,
                                   p_wf + BASE_L + (size_t)(2 * l) * SZ128, mb1 + l * 128,
                                   p_wf + BASE_L + (size_t)(2 * l + 1) * SZ128, mb2 + l * 128,
                                   gamma + l * 128, beta + l * 128, bnscale, p_h);
    }

    // 5) readout + heads
    float* out_f    = (float*)d_out;
    float* out_ge   = out_f + G;              // graph_emb [G,256]
    float* out_comb = out_f + G + G * 256;    // combined  [G,384]

    pool_seg_kernel<<<G, 128>>>(p_h, npg, out_ge);

    dense_relu_kernel<<<(G * 128 + 255) / 256, 256>>>(expf_, ew1, eb1, p_ex1, G, 200, 128);
    dense_relu_kernel<<<(G * 128 + 255) / 256, 256>>>(p_ex1, ew2, eb2, p_ex2, G, 128, 128);
    comb_kernel<<<(G * 384 + 255) / 256, 256>>>(G, out_comb);
    dense_relu_kernel<<<(G * 256 + 255) / 256, 256>>>(p_comb, hw1, hb1, p_o1, G, 384, 256);
    dense_relu_kernel<<<(G * 128 + 255) / 256, 256>>>(p_o1, hw2, hb2, p_o2, G, 256, 128);
    head3_kernel<<<(G + 127) / 128, 128>>>(G, hw3, hb3, out_f);
}

// round 7
// speedup vs baseline: 2.2098x; 1.0788x over previous
#include <cuda_runtime.h>
#include <math.h>

#define HDIM 128
#define LLAYERS 5
#define NMAX 100000
#define EMAX 200000
#define GMAX 2000

// packed (bf16x2) smem strides in u32 units
#define SA_LAYER 68   // 64 data + 4 pad
#define SA_NODE  20   // 16 data + 4 pad

// ---------------- scratch (static device globals; no allocation) ----------------
__device__ float    g_h[NMAX * HDIM];
__device__ float    g_z[NMAX * HDIM];
__device__ float    g_etab[LLAYERS * 24 * HDIM];
__device__ __align__(16) unsigned g_wfrag[368640];   // bf16 hi/lo weight fragments
__device__ float    g_gemb[GMAX * 256];
__device__ float    g_ex1[GMAX * HDIM];
__device__ float    g_ex2[GMAX * HDIM];
__device__ float    g_comb[GMAX * 384];
__device__ float    g_o1[GMAX * 256];
__device__ float    g_o2[GMAX * 128];

// ---------------- helpers ----------------
__device__ __forceinline__ void bf16_split2(float x, float y, unsigned& hi, unsigned& lo) {
    // hi = pack(bf16(y), bf16(x)) : x in low half, y in high half
    asm("cvt.rn.bf16x2.f32 %0, %1, %2;" : "=r"(hi) : "f"(y), "f"(x));
    float hx = __uint_as_float(hi << 16);
    float hy = __uint_as_float(hi & 0xffff0000u);
    float lx = x - hx, ly = y - hy;
    asm("cvt.rn.bf16x2.f32 %0, %1, %2;" : "=r"(lo) : "f"(ly), "f"(lx));
}
__device__ __forceinline__ void mma_bf16(float c[4], const unsigned a[4],
                                         unsigned b0, unsigned b1) {
    asm volatile(
        "mma.sync.aligned.m16n8k16.row.col.f32.bf16.bf16.f32 "
        "{%0,%1,%2,%3}, {%4,%5,%6,%7}, {%8,%9}, {%0,%1,%2,%3};"
        : "+f"(c[0]), "+f"(c[1]), "+f"(c[2]), "+f"(c[3])
        : "r"(a[0]), "r"(a[1]), "r"(a[2]), "r"(a[3]), "r"(b0), "r"(b1));
}
__device__ __forceinline__ unsigned smaddr(const void* p) {
    return (unsigned)__cvta_generic_to_shared(p);
}
__device__ __forceinline__ void ldsm_x4(unsigned a[4], unsigned addr) {
    asm volatile("ldmatrix.sync.aligned.m8n8.x4.shared.b16 {%0,%1,%2,%3}, [%4];"
                 : "=r"(a[0]), "=r"(a[1]), "=r"(a[2]), "=r"(a[3]) : "r"(addr));
}

// ---------------- weight fragment precompute (bf16 hi/lo split) -------------
// W: [K,128] row-major. out[(ks16*16 + ntile)*32 + lane] = uint4{bhi0,bhi1,blo0,blo1}
__global__ void wfrag_kernel(const float* __restrict__ W, unsigned* __restrict__ out)
{
    int ks = blockIdx.x, nt = blockIdx.y, lane = threadIdx.x;
    int n  = nt * 8 + (lane >> 2);
    int k0 = ks * 16 + (lane & 3) * 2;
    float w00 = W[k0 * 128 + n];
    float w01 = W[(k0 + 1) * 128 + n];
    float w10 = W[(k0 + 8) * 128 + n];
    float w11 = W[(k0 + 9) * 128 + n];
    unsigned bh0, bl0, bh1, bl1;
    bf16_split2(w00, w01, bh0, bl0);
    bf16_split2(w10, w11, bh1, bl1);
    unsigned* p = out + ((size_t)(ks * 16 + nt) * 32 + lane) * 4;
    p[0] = bh0; p[1] = bh1; p[2] = bl0; p[3] = bl1;
}

// ---------------- 3x-bf16 tile GEMM using ldmatrix on pre-split tiles -----------
// Ahi/Alo: smem, packed bf16x2, row stride SA u32
template <int K, int SA>
__device__ __forceinline__ void gemm_tile_ldm(const unsigned* Ahi, const unsigned* Alo,
                                              const unsigned* __restrict__ frag,
                                              int rowgrp, int colgrp, int lane,
                                              float acc[2][8][4])
{
    const int lrow = lane & 15;            // row within 16-row half
    const int lcol = (lane >> 4) * 4;      // u32 col offset for k-halves
    #pragma unroll
    for (int ks = 0; ks < K / 16; ks++) {
        unsigned ahi[2][4], alo[2][4];
        #pragma unroll
        for (int mt = 0; mt < 2; mt++) {
            int row = rowgrp * 32 + mt * 16 + lrow;
            unsigned off = 4u * (row * SA + ks * 8 + lcol);
            ldsm_x4(ahi[mt], smaddr(Ahi) + off);
            ldsm_x4(alo[mt], smaddr(Alo) + off);
        }
        #pragma unroll
        for (int t = 0; t < 8; t++) {
            int nt = colgrp * 8 + t;
            const uint4 bf = *(const uint4*)(frag + ((size_t)(ks * 16 + nt) * 32 + lane) * 4);
            #pragma unroll
            for (int mt = 0; mt < 2; mt++) {
                mma_bf16(acc[mt][t], ahi[mt], bf.x, bf.y);   // hi*hi
                mma_bf16(acc[mt][t], ahi[mt], bf.z, bf.w);   // hi*lo
                mma_bf16(acc[mt][t], alo[mt], bf.x, bf.y);   // lo*hi
            }
        }
    }
}

// ---------------- fused 2-GEMM MLP on tensor cores ----------------
// LAYER=true : A_in = A + Aadd; H[r] += relu(bn(mlp(A_in)))   (residual, in place)
// LAYER=false: H[r] = mlp(A)
// ZB != nullptr: zero ZB rows [n0, n0+128) in epilogue (aggr buffer for next layer)
template <int K1, bool LAYER>
__global__ __launch_bounds__(256, 2)
void mlp2_mma_kernel(const float* A, const float* __restrict__ Aadd, int N,
                     const unsigned* __restrict__ frag1, const float* __restrict__ b1,
                     const unsigned* __restrict__ frag2, const float* __restrict__ b2,
                     const float* __restrict__ gamma, const float* __restrict__ beta,
                     float bnscale, float* H, float* __restrict__ ZB)
{
    extern __shared__ unsigned smu[];
    unsigned* Ahi = smu;                  // [128][SA] packed bf16x2 hi
    unsigned* Alo = smu + 128 * SA_LAYER; // [128][SA] packed bf16x2 lo
    const int tid = threadIdx.x, lane = tid & 31, warp = tid >> 5;
    const int rowgrp = warp >> 1, colgrp = warp & 1;
    const int n0 = blockIdx.x * 128;
    const int SA1 = LAYER ? SA_LAYER : SA_NODE;

    // load A tile [128 x K1], split to bf16 hi/lo packed (each element once)
    {
        const int QK = K1 / 4;
        #pragma unroll
        for (int i = 0; i < (128 * QK) / 256; i++) {
            int idx = tid + i * 256;
            int r = idx / QK, cq = idx % QK;
            float4 v = make_float4(0.f, 0.f, 0.f, 0.f);
            if (n0 + r < N) {
                v = *(const float4*)(A + (size_t)(n0 + r) * K1 + cq * 4);
                if (LAYER) {
                    float4 w = *(const float4*)(Aadd + (size_t)(n0 + r) * K1 + cq * 4);
                    v.x += w.x; v.y += w.y; v.z += w.z; v.w += w.w;
                }
            }
            unsigned h0, l0, h1, l1;
            bf16_split2(v.x, v.y, h0, l0);
            bf16_split2(v.z, v.w, h1, l1);
            *(uint2*)(Ahi + r * SA1 + cq * 2) = make_uint2(h0, h1);
            *(uint2*)(Alo + r * SA1 + cq * 2) = make_uint2(l0, l1);
        }
    }
    __syncthreads();

    float acc[2][8][4];
    #pragma unroll
    for (int mt = 0; mt < 2; mt++)
        #pragma unroll
        for (int t = 0; t < 8; t++)
            #pragma unroll
            for (int j = 0; j < 4; j++) acc[mt][t][j] = 0.f;

    if (LAYER) gemm_tile_ldm<128, SA_LAYER>(Ahi, Alo, frag1, rowgrp, colgrp, lane, acc);
    else       gemm_tile_ldm<K1,  SA_NODE >(Ahi, Alo, frag1, rowgrp, colgrp, lane, acc);
    __syncthreads();

    // intermediate: relu(acc + b1), split once in registers -> packed hi/lo (stride 68)
    #pragma unroll
    for (int mt = 0; mt < 2; mt++) {
        #pragma unroll
        for (int t = 0; t < 8; t++) {
            int col = (colgrp * 8 + t) * 8 + 2 * (lane & 3);
            float bb0 = __ldg(b1 + col), bb1 = __ldg(b1 + col + 1);
            int r0 = rowgrp * 32 + mt * 16 + (lane >> 2);
            float z00 = fmaxf(acc[mt][t][0] + bb0, 0.f);
            float z01 = fmaxf(acc[mt][t][1] + bb1, 0.f);
            float z10 = fmaxf(acc[mt][t][2] + bb0, 0.f);
            float z11 = fmaxf(acc[mt][t][3] + bb1, 0.f);
            unsigned h, l;
            bf16_split2(z00, z01, h, l);
            Ahi[r0 * SA_LAYER + col / 2] = h;
            Alo[r0 * SA_LAYER + col / 2] = l;
            bf16_split2(z10, z11, h, l);
            Ahi[(r0 + 8) * SA_LAYER + col / 2] = h;
            Alo[(r0 + 8) * SA_LAYER + col / 2] = l;
        }
    }
    __syncthreads();

    #pragma unroll
    for (int mt = 0; mt < 2; mt++)
        #pragma unroll
        for (int t = 0; t < 8; t++)
            #pragma unroll
            for (int j = 0; j < 4; j++) acc[mt][t][j] = 0.f;

    gemm_tile_ldm<128, SA_LAYER>(Ahi, Alo, frag2, rowgrp, colgrp, lane, acc);

    // epilogue
    #pragma unroll
    for (int mt = 0; mt < 2; mt++) {
        #pragma unroll
        for (int t = 0; t < 8; t++) {
            int col = (colgrp * 8 + t) * 8 + 2 * (lane & 3);
            float bb0 = __ldg(b2 + col), bb1 = __ldg(b2 + col + 1);
            int r0 = rowgrp * 32 + mt * 16 + (lane >> 2);
            if (LAYER) {
                float gm0 = __ldg(gamma + col) * bnscale, gm1 = __ldg(gamma + col + 1) * bnscale;
                float bt0 = __ldg(beta + col), bt1 = __ldg(beta + col + 1);
                #pragma unroll
                for (int half = 0; half < 2; half++) {
                    int row = n0 + r0 + 8 * half;
                    if (row < N) {
                        float z0 = fmaxf((acc[mt][t][2 * half + 0] + bb0) * gm0 + bt0, 0.f);
                        float z1 = fmaxf((acc[mt][t][2 * half + 1] + bb1) * gm1 + bt1, 0.f);
                        float* hp = H + (size_t)row * 128 + col;
                        float2 hv = *(float2*)hp;     // h_in (residual)
                        hv.x += z0; hv.y += z1;
                        *(float2*)hp = hv;
                    }
                }
            } else {
                #pragma unroll
                for (int half = 0; half < 2; half++) {
                    int row = n0 + r0 + 8 * half;
                    if (row < N) {
                        float2 o;
                        o.x = acc[mt][t][2 * half + 0] + bb0;
                        o.y = acc[mt][t][2 * half + 1] + bb1;
                        *(float2*)(H + (size_t)row * 128 + col) = o;
                    }
                }
            }
        }
    }

    // fused zero of aggregation buffer for next layer's msg scatter
    if (ZB != nullptr) {
        const float4 zv = make_float4(0.f, 0.f, 0.f, 0.f);
        #pragma unroll
        for (int i = 0; i < 16; i++) {
            int idx = tid + i * 256;
            int r = idx >> 5, cq = idx & 31;
            if (n0 + r < N)
                *(float4*)(ZB + (size_t)(n0 + r) * 128 + cq * 4) = zv;
        }
    }
}

// ---------------- edge-type table: etab[l][t] = (te[bt]+de[bd]) @ lew[l] + leb[l] --
__global__ void etab_kernel(const float* __restrict__ te, const float* __restrict__ de,
                            const float* __restrict__ lew, const float* __restrict__ leb)
{
    int l = blockIdx.x / 24, t = blockIdx.x % 24;
    int bt = t / 4, bd = t % 4;
    int c = threadIdx.x;
    float s = leb[l * 128 + c];
    #pragma unroll 4
    for (int k = 0; k < 64; k++) {
        float ev = te[bt * 64 + k] + de[bd * 64 + k];
        s += ev * __ldg(lew + (size_t)(l * 64 + k) * 128 + c);
    }
    g_etab[(l * 24 + t) * 128 + c] = s;
}

// ---------------- message + scatter: z[dst] += relu(h[src] + etab[type]) ----------
__global__ void msg_kernel(const int* __restrict__ ei, const int* __restrict__ ea,
                           const float* __restrict__ etab_l, int E,
                           const float* __restrict__ h, float* __restrict__ z)
{
    int e = blockIdx.x * 8 + (threadIdx.x >> 5);
    if (e >= E) return;
    int lane = threadIdx.x & 31;
    int src = ei[e], dst = ei[E + e];
    int bt = ea[2 * e], bd = ea[2 * e + 1];
    bt = min(max(bt, 0), 5);
    bd = min(max(bd, 0), 3);
    const float* et = etab_l + (bt * 4 + bd) * 128;
    float4 hv = *(const float4*)(h + (size_t)src * 128 + lane * 4);
    float4 ev = *(const float4*)(et + lane * 4);
    float m0 = fmaxf(hv.x + ev.x, 0.f);
    float m1 = fmaxf(hv.y + ev.y, 0.f);
    float m2 = fmaxf(hv.z + ev.z, 0.f);
    float m3 = fmaxf(hv.w + ev.w, 0.f);
    float* zp = z + (size_t)dst * 128 + lane * 4;
    asm volatile("red.global.add.v4.f32 [%0], {%1,%2,%3,%4};"
                 :: "l"(zp), "f"(m0), "f"(m1), "f"(m2), "f"(m3) : "memory");
}

// ---------------- segmented pooling (batch is contiguous, npg nodes/graph) -------
__global__ void pool_seg_kernel(const float* __restrict__ h, int npg, float* __restrict__ out_ge)
{
    int g = blockIdx.x, c = threadIdx.x;
    const float* p = h + (size_t)g * npg * 128 + c;
    float s = 0.f, m = -INFINITY;
    for (int i = 0; i < npg; i++) {
        float v = p[(size_t)i * 128];
        s += v;
        m = fmaxf(m, v);
    }
    float mean = s / (float)npg;
    g_gemb[g * 256 + c] = mean;
    g_gemb[g * 256 + 128 + c] = m;
    out_ge[g * 256 + c] = mean;
    out_ge[g * 256 + 128 + c] = m;
}

// ---------------- small dense layers (naive, tiny G) ----------------
__global__ void dense_relu_kernel(const float* __restrict__ X, const float* __restrict__ W,
                                  const float* __restrict__ b, float* __restrict__ Y,
                                  int G, int K, int C)
{
    int idx = blockIdx.x * blockDim.x + threadIdx.x;
    if (idx >= G * C) return;
    int g = idx / C, c = idx % C;
    float s = __ldg(b + c);
    #pragma unroll 4
    for (int k = 0; k < K; k++)
        s += __ldg(X + (size_t)g * K + k) * __ldg(W + (size_t)k * C + c);
    Y[idx] = fmaxf(s, 0.f);
}

__global__ void comb_kernel(int G, float* __restrict__ out_comb)
{
    int idx = blockIdx.x * blockDim.x + threadIdx.x;
    if (idx >= G * 384) return;
    int g = idx / 384, c = idx % 384;
    float v = (c < 256) ? g_gemb[g * 256 + c] : g_ex2[g * 128 + (c - 256)];
    g_comb[idx] = v;
    out_comb[idx] = v;
}

__global__ void head3_kernel(int G, const float* __restrict__ hw3,
                             const float* __restrict__ hb3, float* __restrict__ out)
{
    int g = blockIdx.x * blockDim.x + threadIdx.x;
    if (g >= G) return;
    float s = __ldg(hb3);
    #pragma unroll 4
    for (int k = 0; k < 128; k++)
        s += g_o2[g * 128 + k] * __ldg(hw3 + k);
    out[g] = s;
}

// ---------------- launch ----------------
extern "C" void kernel_launch(void* const* d_in, const int* in_sizes, int n_in,
                              void* d_out, int out_size)
{
    const float* x     = (const float*)d_in[0];
    const int*   ei    = (const int*)d_in[1];
    const int*   ea    = (const int*)d_in[2];
    const float* expf_ = (const float*)d_in[4];
    const float* nw1 = (const float*)d_in[5];
    const float* nb1 = (const float*)d_in[6];
    const float* nw2 = (const float*)d_in[7];
    const float* nb2 = (const float*)d_in[8];
    const float* te  = (const float*)d_in[9];
    const float* de  = (const float*)d_in[10];
    const float* lew = (const float*)d_in[11];
    const float* leb = (const float*)d_in[12];
    const float* mw1 = (const float*)d_in[13];
    const float* mb1 = (const float*)d_in[14];
    const float* mw2 = (const float*)d_in[15];
    const float* mb2 = (const float*)d_in[16];
    const float* gamma = (const float*)d_in[17];
    const float* beta  = (const float*)d_in[18];
    const float* ew1 = (const float*)d_in[19];
    const float* eb1 = (const float*)d_in[20];
    const float* ew2 = (const float*)d_in[21];
    const float* eb2 = (const float*)d_in[22];
    const float* hw1 = (const float*)d_in[23];
    const float* hb1 = (const float*)d_in[24];
    const float* hw2 = (const float*)d_in[25];
    const float* hb2 = (const float*)d_in[26];
    const float* hw3 = (const float*)d_in[27];
    const float* hb3 = (const float*)d_in[28];

    const int N = in_sizes[0] / 32;
    const int E = in_sizes[1] / 2;
    const int G = in_sizes[4] / 200;
    const int npg = N / G;
    const float bnscale = 1.0f / sqrtf(1.0f + 1e-5f);

    float*    p_h;     cudaGetSymbolAddress((void**)&p_h, g_h);
    float*    p_z;     cudaGetSymbolAddress((void**)&p_z, g_z);
    float*    p_etab;  cudaGetSymbolAddress((void**)&p_etab, g_etab);
    unsigned* p_wf;    cudaGetSymbolAddress((void**)&p_wf, g_wfrag);
    float*    p_ex1;   cudaGetSymbolAddress((void**)&p_ex1, g_ex1);
    float*    p_ex2;   cudaGetSymbolAddress((void**)&p_ex2, g_ex2);
    float*    p_comb;  cudaGetSymbolAddress((void**)&p_comb, g_comb);
    float*    p_o1;    cudaGetSymbolAddress((void**)&p_o1, g_o1);
    float*    p_o2;    cudaGetSymbolAddress((void**)&p_o2, g_o2);

    // fragment buffer offsets (u32): node1 (K=32: 2 ks16) @0, node2 @4096,
    // per-layer mw1/mw2 (8 ks16 = 16384 u32 each) from 20480
    const size_t OFF_N1 = 0;
    const size_t OFF_N2 = 4096;
    const size_t BASE_L = 20480;
    const size_t SZ128  = 16384;

    // 1) build weight fragment tables (bf16 hi/lo split)
    wfrag_kernel<<<dim3(2, 16), 32>>>(nw1, p_wf + OFF_N1);
    wfrag_kernel<<<dim3(8, 16), 32>>>(nw2, p_wf + OFF_N2);
    for (int l = 0; l < LLAYERS; l++) {
        wfrag_kernel<<<dim3(8, 16), 32>>>(mw1 + (size_t)l * 128 * 128,
                                          p_wf + BASE_L + (size_t)(2 * l) * SZ128);
        wfrag_kernel<<<dim3(8, 16), 32>>>(mw2 + (size_t)l * 128 * 128,
                                          p_wf + BASE_L + (size_t)(2 * l + 1) * SZ128);
    }
    // 2) edge type tables
    etab_kernel<<<LLAYERS * 24, 128>>>(te, de, lew, leb);

    auto kNode  = mlp2_mma_kernel<32, false>;
    auto kLayer = mlp2_mma_kernel<128, true>;
    const int SMEM = 2 * 128 * SA_LAYER * 4;   // 69632 B
    cudaFuncSetAttribute((const void*)kNode,  cudaFuncAttributeMaxDynamicSharedMemorySize, SMEM);
    cudaFuncSetAttribute((const void*)kLayer, cudaFuncAttributeMaxDynamicSharedMemorySize, SMEM);

    const int nb = (N + 127) / 128;

    // 3) node projection MLP -> g_h  (also zeroes z for layer 0's scatter)
    kNode<<<nb, 256, SMEM>>>(x, nullptr, N, p_wf + OFF_N1, nb1, p_wf + OFF_N2, nb2,
                             nullptr, nullptr, 1.f, p_h, p_z);

    // 4) GINE layers (each MLP re-zeroes z for the next layer; last one skips)
    for (int l = 0; l < LLAYERS; l++) {
        msg_kernel<<<(E + 7) / 8, 256>>>(ei, ea, p_etab + (size_t)l * 24 * 128, E, p_h, p_z);
        kLayer<<<nb, 256, SMEM>>>(p_h, p_z, N,
                                  p_wf + BASE_L + (size_t)(2 * l) * SZ128, mb1 + l * 128,
                                  p_wf + BASE_L + (size_t)(2 * l + 1) * SZ128, mb2 + l * 128,
                                  gamma + l * 128, beta + l * 128, bnscale, p_h,
                                  (l + 1 < LLAYERS) ? p_z : nullptr);
    }

    // 5) readout + heads
    float* out_f    = (float*)d_out;
    float* out_ge   = out_f + G;              // graph_emb [G,256]
    float* out_comb = out_f + G + G * 256;    // combined  [G,384]

    pool_seg_kernel<<<G, 128>>>(p_h, npg, out_ge);

    dense_relu_kernel<<<(G * 128 + 255) / 256, 256>>>(expf_, ew1, eb1, p_ex1, G, 200, 128);
    dense_relu_kernel<<<(G * 128 + 255) / 256, 256>>>(p_ex1, ew2, eb2, p_ex2, G, 128, 128);
    comb_kernel<<<(G * 384 + 255) / 256, 256>>>(G, out_comb);
    dense_relu_kernel<<<(G * 256 + 255) / 256, 256>>>(p_comb, hw1, hb1, p_o1, G, 384, 256);
    dense_relu_kernel<<<(G * 128 + 255) / 256, 256>>>(p_o1, hw2, hb2, p_o2, G, 256, 128);
    head3_kernel<<<(G + 127) / 128, 128>>>(G, hw3, hb3, out_f);
}